// round 5
// baseline (speedup 1.0000x reference)
#include <cuda_runtime.h>
#include <cstdint>

// Problem constants
#define BB 2
#define TT 2048
#define CC 1024
#define HH 16
#define DH 64
#define BH (BB*HH)   // 32

// Output layout (tuple flattened): out, dist_energy, flop_energy, repulsion, attn, dists
#define OUT_OFF   0
#define SCAL_OFF  4194304
#define ATTN_OFF  4194307ull      // ≡3 mod 4 → attn region only 4B-aligned
#define DIST_OFF  138412035ull    // ≡3 mod 4 → dists region only 4B-aligned

#define NEGINF (-__int_as_float(0x7f800000))

// Scratch (static device memory — all 16B-aligned)
__device__ float g_q[BH * TT * DH];
__device__ float g_k[BH * TT * DH];
__device__ float g_v[BH * TT * DH];
__device__ float g_oh[BB * TT * CC];         // head outputs in [B,T,C] layout
__device__ float g_d [TT * TT];              // aligned dists copy
__device__ float g_l [(size_t)BH * TT * TT]; // staged e = exp(v - m_tile), lower tiles only
__device__ float g_repp[TT];
// per-(row, 128-tile) partials: [bh][t][tile]
__device__ float g_mp[BH * TT * 16];
__device__ float g_s1[BH * TT * 16];
__device__ float g_s2[BH * TT * 16];
__device__ float g_s3[BH * TT * 16];
__device__ float g_c [BH * TT * 16];         // C = exp(m_tile - m)/l
__device__ float g_edp[256];
__device__ float g_efp[256];

// ---------------------------------------------------------------------------
// tf32 helpers — hi/lo pair packed in uint2 (x=hi, y=lo)
// ---------------------------------------------------------------------------
__device__ __forceinline__ uint32_t f2tf32(float v) {
    uint32_t r;
    asm("cvt.rna.tf32.f32 %0, %1;" : "=r"(r) : "f"(v));
    return r;
}

__device__ __forceinline__ uint2 hl2(float v) {
    uint32_t h = f2tf32(v);
    return make_uint2(h, f2tf32(v - __uint_as_float(h)));
}

#define MMA_TF32(C, A0,A1,A2,A3, B0,B1)                                        \
    asm volatile("mma.sync.aligned.m16n8k8.row.col.f32.tf32.tf32.f32 "         \
        "{%0,%1,%2,%3}, {%4,%5,%6,%7}, {%8,%9}, {%0,%1,%2,%3};"                \
        : "+f"((C)[0]), "+f"((C)[1]), "+f"((C)[2]), "+f"((C)[3])               \
        : "r"(A0), "r"(A1), "r"(A2), "r"(A3), "r"(B0), "r"(B1))

// one k=8 step of the 128x128 block tile (3xTF32), warp tile 64x32
__device__ __forceinline__ void mma_step(
    const uint2 (*A2)[132], const uint2 (*B2)[132],
    int kk, int wm, int wn, int g, int t4, float c[4][4][4])
{
    uint32_t ah[4][4], al[4][4], bh[4][2], bl[4][2];
#pragma unroll
    for (int i = 0; i < 4; i++) {
        const int rb = wm*64 + i*16 + g;
        uint2 x0 = A2[kk+t4  ][rb];
        uint2 x1 = A2[kk+t4  ][rb+8];
        uint2 x2 = A2[kk+t4+4][rb];
        uint2 x3 = A2[kk+t4+4][rb+8];
        ah[i][0] = x0.x; ah[i][1] = x1.x; ah[i][2] = x2.x; ah[i][3] = x3.x;
        al[i][0] = x0.y; al[i][1] = x1.y; al[i][2] = x2.y; al[i][3] = x3.y;
    }
#pragma unroll
    for (int j = 0; j < 4; j++) {
        const int cb = wn*32 + j*8 + g;
        uint2 y0 = B2[kk+t4  ][cb];
        uint2 y1 = B2[kk+t4+4][cb];
        bh[j][0] = y0.x; bh[j][1] = y1.x;
        bl[j][0] = y0.y; bl[j][1] = y1.y;
    }
#pragma unroll
    for (int i = 0; i < 4; i++)
#pragma unroll
        for (int j = 0; j < 4; j++) {
            MMA_TF32(c[i][j], ah[i][0],ah[i][1],ah[i][2],ah[i][3], bh[j][0],bh[j][1]);
            MMA_TF32(c[i][j], ah[i][0],ah[i][1],ah[i][2],ah[i][3], bl[j][0],bl[j][1]);
            MMA_TF32(c[i][j], al[i][0],al[i][1],al[i][2],al[i][3], bh[j][0],bh[j][1]);
        }
}

// stage a float4 (4 consecutive k values for one row) into the uint2 tile
__device__ __forceinline__ void stage4(uint2 (*S)[132], int k, int idx, float4 v) {
    S[k+0][idx] = hl2(v.x);
    S[k+1][idx] = hl2(v.y);
    S[k+2][idx] = hl2(v.z);
    S[k+3][idx] = hl2(v.w);
}

// ---------------------------------------------------------------------------
// K1: QKV = X @ W^T  (M=4096, N=3072, K=1024) via 3xTF32, route to q/k/v
// ---------------------------------------------------------------------------
__global__ __launch_bounds__(256) void k_qkv(const float* __restrict__ X,
                                             const float* __restrict__ W) {
    __shared__ uint2 A2[16][132];
    __shared__ uint2 B2[16][132];
    const int tid = threadIdx.x;
    const int warp = tid >> 5, lane = tid & 31;
    const int wm = warp >> 2, wn = warp & 3;
    const int g = lane >> 2, t4 = lane & 3;
    const int m0 = blockIdx.y * 128;
    const int n0 = blockIdx.x * 128;
    const int r = tid >> 2, c4 = (tid & 3) * 4;

    float c[4][4][4];
#pragma unroll
    for (int i = 0; i < 4; i++)
#pragma unroll
        for (int j = 0; j < 4; j++)
#pragma unroll
            for (int q = 0; q < 4; q++) c[i][j][q] = 0.f;

    for (int k0 = 0; k0 < 1024; k0 += 16) {
        float4 a0 = *(const float4*)(X + (size_t)(m0 + r)      * 1024 + k0 + c4);
        float4 a1 = *(const float4*)(X + (size_t)(m0 + r + 64) * 1024 + k0 + c4);
        float4 b0 = *(const float4*)(W + (size_t)(n0 + r)      * 1024 + k0 + c4);
        float4 b1 = *(const float4*)(W + (size_t)(n0 + r + 64) * 1024 + k0 + c4);
        __syncthreads();
        stage4(A2, c4, r, a0);  stage4(A2, c4, r + 64, a1);
        stage4(B2, c4, r, b0);  stage4(B2, c4, r + 64, b1);
        __syncthreads();
        mma_step(A2, B2, 0, wm, wn, g, t4, c);
        mma_step(A2, B2, 8, wm, wn, g, t4, c);
    }

    const int which = n0 >> 10;
    float* dst = (which == 0) ? g_q : (which == 1) ? g_k : g_v;
#pragma unroll
    for (int i = 0; i < 4; i++) {
        const int gi0 = m0 + wm*64 + i*16 + g;
        const int gi1 = gi0 + 8;
        const int b0i = gi0 >> 11, t0i = gi0 & 2047;
        const int b1i = gi1 >> 11, t1i = gi1 & 2047;
#pragma unroll
        for (int j = 0; j < 4; j++) {
            const int col = n0 + wn*32 + j*8 + 2*t4;
            const int cl = col & 1023;
            const int h = cl >> 6, d = cl & 63;
            *(float2*)(dst + ((size_t)(b0i*16 + h) * TT + t0i) * DH + d) =
                make_float2(c[i][j][0], c[i][j][1]);
            *(float2*)(dst + ((size_t)(b1i*16 + h) * TT + t1i) * DH + d) =
                make_float2(c[i][j][2], c[i][j][3]);
        }
    }
}

// ---------------------------------------------------------------------------
// K2: pairwise dists (grad-safe) + repulsion partials
// ---------------------------------------------------------------------------
__global__ __launch_bounds__(256) void k_dists(const float* __restrict__ pos,
                                               float* __restrict__ Dd) {
    __shared__ float sm[256];
    const int t = blockIdx.x;
    const float px = pos[t*3+0], py = pos[t*3+1], pz = pos[t*3+2];
    float rep = 0.f;
    for (int s = threadIdx.x; s < TT; s += 256) {
        float dx = px - pos[s*3+0];
        float dy = py - pos[s*3+1];
        float dz = pz - pos[s*3+2];
        float sq = dx*dx + dy*dy + dz*dz;
        float d = (sq > 0.f) ? sqrtf(sq) : 0.f;
        Dd[(size_t)t * TT + s] = d;   // scalar: output region only 4B-aligned
        g_d[(size_t)t * TT + s] = d;
        if (s != t) rep += 1.f / (d + 1e-4f);
    }
    sm[threadIdx.x] = rep;
    __syncthreads();
    for (int s = 128; s; s >>= 1) {
        if (threadIdx.x < s) sm[threadIdx.x] += sm[threadIdx.x + s];
        __syncthreads();
    }
    if (threadIdx.x == 0) g_repp[t] = sm[0];
}

// ---------------------------------------------------------------------------
// K3: logits GEMM (3xTF32) + fused tile-softmax partials.
// Stores e = exp(v - m_tile) into g_l, partials (m,S1,S2,S3) per (row,tile).
// Only lower-triangle+diag 128x128 tiles (136 per head).
// ---------------------------------------------------------------------------
__global__ __launch_bounds__(256) void k_logits() {
    const int bh = blockIdx.y;
    const int p  = blockIdx.x;
    int it = (int)((sqrtf(8.f * p + 1.f) - 1.f) * 0.5f);
    while ((it + 1) * (it + 2) / 2 <= p) it++;
    while (it * (it + 1) / 2 > p) it--;
    const int jt = p - it * (it + 1) / 2;
    const int m0 = it * 128;
    const int n0 = jt * 128;

    float* Lp = g_l + (size_t)bh * TT * TT;
    const float* Q  = g_q + (size_t)bh * TT * DH;
    const float* Kp = g_k + (size_t)bh * TT * DH;

    __shared__ uint2 A2[16][132];
    __shared__ uint2 B2[16][132];
    __shared__ float red0[4][128];
    __shared__ float redS1[4][128], redS2[4][128], redS3[4][128];
    __shared__ float rowm[128];

    const int tid = threadIdx.x;
    const int warp = tid >> 5, lane = tid & 31;
    const int wm = warp >> 2, wn = warp & 3;
    const int g = lane >> 2, t4 = lane & 3;
    const int r = tid >> 2, c4 = (tid & 3) * 4;

    float c[4][4][4];
#pragma unroll
    for (int i = 0; i < 4; i++)
#pragma unroll
        for (int j = 0; j < 4; j++)
#pragma unroll
            for (int q = 0; q < 4; q++) c[i][j][q] = 0.f;

#pragma unroll
    for (int k0 = 0; k0 < 64; k0 += 16) {
        float4 a0 = *(const float4*)(Q  + (size_t)(m0 + r)      * DH + k0 + c4);
        float4 a1 = *(const float4*)(Q  + (size_t)(m0 + r + 64) * DH + k0 + c4);
        float4 b0 = *(const float4*)(Kp + (size_t)(n0 + r)      * DH + k0 + c4);
        float4 b1 = *(const float4*)(Kp + (size_t)(n0 + r + 64) * DH + k0 + c4);
        __syncthreads();
        stage4(A2, c4, r, a0);  stage4(A2, c4, r + 64, a1);
        stage4(B2, c4, r, b0);  stage4(B2, c4, r + 64, b1);
        __syncthreads();
        mma_step(A2, B2, 0, wm, wn, g, t4, c);
        mma_step(A2, B2, 8, wm, wn, g, t4, c);
    }

    // ---- Phase 1: v = qk/8 - d (mask -> -inf), per-row max ----
    float rmax[8];
#pragma unroll
    for (int q = 0; q < 8; q++) rmax[q] = NEGINF;
#pragma unroll
    for (int i = 0; i < 4; i++) {
        const int lr0 = wm*64 + i*16 + g;
        const int t0g = m0 + lr0, t1g = t0g + 8;
#pragma unroll
        for (int j = 0; j < 4; j++) {
            const int s = n0 + wn*32 + j*8 + 2*t4;
            const float2 d0 = *(const float2*)(g_d + (size_t)t0g * TT + s);
            const float2 d1 = *(const float2*)(g_d + (size_t)t1g * TT + s);
            float v0 = c[i][j][0]*0.125f - d0.x; if (s     > t0g) v0 = NEGINF;
            float v1 = c[i][j][1]*0.125f - d0.y; if (s + 1 > t0g) v1 = NEGINF;
            float v2 = c[i][j][2]*0.125f - d1.x; if (s     > t1g) v2 = NEGINF;
            float v3 = c[i][j][3]*0.125f - d1.y; if (s + 1 > t1g) v3 = NEGINF;
            c[i][j][0] = v0; c[i][j][1] = v1; c[i][j][2] = v2; c[i][j][3] = v3;
            rmax[2*i]   = fmaxf(rmax[2*i],   fmaxf(v0, v1));
            rmax[2*i+1] = fmaxf(rmax[2*i+1], fmaxf(v2, v3));
        }
    }
#pragma unroll
    for (int q = 0; q < 8; q++) {
        rmax[q] = fmaxf(rmax[q], __shfl_xor_sync(0xffffffffu, rmax[q], 1));
        rmax[q] = fmaxf(rmax[q], __shfl_xor_sync(0xffffffffu, rmax[q], 2));
    }
    if (t4 == 0) {
#pragma unroll
        for (int i = 0; i < 4; i++) {
            red0[wn][wm*64 + i*16 + g]     = rmax[2*i];
            red0[wn][wm*64 + i*16 + g + 8] = rmax[2*i+1];
        }
    }
    __syncthreads();
    if (tid < 128)
        rowm[tid] = fmaxf(fmaxf(red0[0][tid], red0[1][tid]),
                          fmaxf(red0[2][tid], red0[3][tid]));
    __syncthreads();

    // ---- Phase 2: e = exp(v - m_tile), store to g_l, partial sums ----
    float s1[8], s2[8], s3[8];
#pragma unroll
    for (int q = 0; q < 8; q++) { s1[q] = 0.f; s2[q] = 0.f; s3[q] = 0.f; }
#pragma unroll
    for (int i = 0; i < 4; i++) {
        const int lr0 = wm*64 + i*16 + g;
        const int t0g = m0 + lr0, t1g = t0g + 8;
        const float mr0 = rowm[lr0], mr1 = rowm[lr0 + 8];
#pragma unroll
        for (int j = 0; j < 4; j++) {
            const int s = n0 + wn*32 + j*8 + 2*t4;
            const float2 d0 = *(const float2*)(g_d + (size_t)t0g * TT + s);
            const float2 d1 = *(const float2*)(g_d + (size_t)t1g * TT + s);
            float e0 = 0.f, e1 = 0.f, e2 = 0.f, e3 = 0.f;
            if (s     <= t0g) { float xm = c[i][j][0] - mr0; e0 = __expf(xm);
                                s1[2*i] += e0; s2[2*i] += e0*xm; s3[2*i] += e0*d0.x; }
            if (s + 1 <= t0g) { float xm = c[i][j][1] - mr0; e1 = __expf(xm);
                                s1[2*i] += e1; s2[2*i] += e1*xm; s3[2*i] += e1*d0.y; }
            if (s     <= t1g) { float xm = c[i][j][2] - mr1; e2 = __expf(xm);
                                s1[2*i+1] += e2; s2[2*i+1] += e2*xm; s3[2*i+1] += e2*d1.x; }
            if (s + 1 <= t1g) { float xm = c[i][j][3] - mr1; e3 = __expf(xm);
                                s1[2*i+1] += e3; s2[2*i+1] += e3*xm; s3[2*i+1] += e3*d1.y; }
            *(float2*)(Lp + (size_t)t0g * TT + s) = make_float2(e0, e1);
            *(float2*)(Lp + (size_t)t1g * TT + s) = make_float2(e2, e3);
        }
    }
#pragma unroll
    for (int q = 0; q < 8; q++) {
        s1[q] += __shfl_xor_sync(0xffffffffu, s1[q], 1);
        s1[q] += __shfl_xor_sync(0xffffffffu, s1[q], 2);
        s2[q] += __shfl_xor_sync(0xffffffffu, s2[q], 1);
        s2[q] += __shfl_xor_sync(0xffffffffu, s2[q], 2);
        s3[q] += __shfl_xor_sync(0xffffffffu, s3[q], 1);
        s3[q] += __shfl_xor_sync(0xffffffffu, s3[q], 2);
    }
    if (t4 == 0) {
#pragma unroll
        for (int i = 0; i < 4; i++) {
            const int r0 = wm*64 + i*16 + g;
            redS1[wn][r0] = s1[2*i];   redS1[wn][r0+8] = s1[2*i+1];
            redS2[wn][r0] = s2[2*i];   redS2[wn][r0+8] = s2[2*i+1];
            redS3[wn][r0] = s3[2*i];   redS3[wn][r0+8] = s3[2*i+1];
        }
    }
    __syncthreads();
    if (tid < 128) {
        const size_t ix = ((size_t)bh * TT + m0 + tid) * 16 + jt;
        g_mp[ix] = rowm[tid];
        g_s1[ix] = redS1[0][tid] + redS1[1][tid] + redS1[2][tid] + redS1[3][tid];
        g_s2[ix] = redS2[0][tid] + redS2[1][tid] + redS2[2][tid] + redS2[3][tid];
        g_s3[ix] = redS3[0][tid] + redS3[1][tid] + redS3[2][tid] + redS3[3][tid];
    }
}

// ---------------------------------------------------------------------------
// K3b: combine per-tile partials -> per-(row,tile) C, per-row energies;
//      block-reduce energies deterministically.
// ---------------------------------------------------------------------------
__global__ __launch_bounds__(256) void k_rowstats() {
    __shared__ float sred[256];
    const int gid = blockIdx.x * 256 + threadIdx.x;   // 65536 rows
    const int t = gid & 2047;
    const int ntile = (t >> 7) + 1;
    const size_t base = (size_t)gid * 16;

    float m = NEGINF;
    for (int j = 0; j < ntile; j++) m = fmaxf(m, g_mp[base + j]);
    float l = 0.f;
    for (int j = 0; j < ntile; j++) l += g_s1[base + j] * __expf(g_mp[base + j] - m);
    const float li = 1.f / l;
    const float ll = __logf(l);

    float ed = 0.f, ef = 0.f;
    for (int j = 0; j < ntile; j++) {
        const float dm = g_mp[base + j] - m;
        const float C = __expf(dm) * li;
        g_c[base + j] = C;
        ed += C * g_s3[base + j];
        ef += C * (g_s2[base + j] + (dm - ll) * g_s1[base + j]);
    }

    sred[threadIdx.x] = ed;
    __syncthreads();
    for (int s = 128; s; s >>= 1) {
        if (threadIdx.x < s) sred[threadIdx.x] += sred[threadIdx.x + s];
        __syncthreads();
    }
    if (threadIdx.x == 0) g_edp[blockIdx.x] = sred[0];
    __syncthreads();
    sred[threadIdx.x] = ef;
    __syncthreads();
    for (int s = 128; s; s >>= 1) {
        if (threadIdx.x < s) sred[threadIdx.x] += sred[threadIdx.x + s];
        __syncthreads();
    }
    if (threadIdx.x == 0) g_efp[blockIdx.x] = sred[0];
}

// ---------------------------------------------------------------------------
// K4: p = e * C  (attn write, scalar) + O = P@V.  No exp, no energies.
// ---------------------------------------------------------------------------
__global__ __launch_bounds__(256) void k_softmax_av(float* __restrict__ attn) {
    const int bh = blockIdx.y;
    const int t0 = (int)(gridDim.x - 1 - blockIdx.x) * 64;  // heavy first
    const int b = bh >> 4, h = bh & 15;
    const float* L = g_l + (size_t)bh * TT * TT;
    float* A = attn + (size_t)bh * TT * TT;
    const float* V = g_v + (size_t)bh * TT * DH;

    __shared__ float Cs[64];
    __shared__ float Ps[64][68];
    __shared__ float Vs[64][68];

    const int tid = threadIdx.x;
    const int ty = tid >> 4, tx = tid & 15;

    float acc[4][4];
#pragma unroll
    for (int i = 0; i < 4; i++)
#pragma unroll
        for (int j = 0; j < 4; j++) acc[i][j] = 0.f;

    const int nt = t0 + 64;
    for (int s0 = 0; s0 < nt; s0 += 64) {
        __syncthreads();
        if (tid < 64)
            Cs[tid] = g_c[((size_t)bh * TT + t0 + tid) * 16 + (s0 >> 7)];
        __syncthreads();
#pragma unroll 4
        for (int e = tid; e < 1024; e += 256) {
            const int rl = e >> 4, cidx = (e & 15) * 4;
            const size_t gix = (size_t)(t0 + rl) * TT + s0 + cidx;
            float4 e4 = *(const float4*)(L + gix);
            const float Cc = Cs[rl];
            float4 p4 = make_float4(e4.x * Cc, e4.y * Cc, e4.z * Cc, e4.w * Cc);
            A[gix]     = p4.x;    // scalar stores: attn region only 4B-aligned
            A[gix + 1] = p4.y;
            A[gix + 2] = p4.z;
            A[gix + 3] = p4.w;
            *(float4*)&Ps[rl][cidx] = p4;
        }
#pragma unroll 4
        for (int e = tid; e < 1024; e += 256) {
            const int ss = e >> 4, d = (e & 15) * 4;
            *(float4*)&Vs[ss][d] = *(const float4*)(V + (size_t)(s0 + ss) * DH + d);
        }
        __syncthreads();
#pragma unroll 4
        for (int ss = 0; ss < 64; ss++) {
            float4 v4 = *(const float4*)&Vs[ss][tx * 4];
            float p0 = Ps[ty*4+0][ss];
            float p1 = Ps[ty*4+1][ss];
            float p2 = Ps[ty*4+2][ss];
            float p3 = Ps[ty*4+3][ss];
            acc[0][0] += p0*v4.x; acc[0][1] += p0*v4.y; acc[0][2] += p0*v4.z; acc[0][3] += p0*v4.w;
            acc[1][0] += p1*v4.x; acc[1][1] += p1*v4.y; acc[1][2] += p1*v4.z; acc[1][3] += p1*v4.w;
            acc[2][0] += p2*v4.x; acc[2][1] += p2*v4.y; acc[2][2] += p2*v4.z; acc[2][3] += p2*v4.w;
            acc[3][0] += p3*v4.x; acc[3][1] += p3*v4.y; acc[3][2] += p3*v4.z; acc[3][3] += p3*v4.w;
        }
    }

    // zero-fill fully-masked attn region (scalar coalesced)
    if (nt < TT) {
        const int nrem = TT - nt;
        for (int q = tid; q < 64 * nrem; q += 256) {
            const int rl = q / nrem;
            const int s  = q - rl * nrem;
            A[(size_t)(t0 + rl) * TT + nt + s] = 0.f;
        }
    }

#pragma unroll
    for (int i = 0; i < 4; i++) {
        const size_t row = (size_t)(b * TT + t0 + ty*4 + i) * CC + h * DH + tx * 4;
        *(float4*)(g_oh + row) = make_float4(acc[i][0], acc[i][1], acc[i][2], acc[i][3]);
    }
}

// ---------------------------------------------------------------------------
// K5: out = g_oh @ proj_w^T  (M=4096, N=1024, K=1024) via 3xTF32
// ---------------------------------------------------------------------------
__global__ __launch_bounds__(256) void k_proj(const float* __restrict__ W,
                                              float* __restrict__ Cout) {
    __shared__ uint2 A2[16][132];
    __shared__ uint2 B2[16][132];
    const int tid = threadIdx.x;
    const int warp = tid >> 5, lane = tid & 31;
    const int wm = warp >> 2, wn = warp & 3;
    const int g = lane >> 2, t4 = lane & 3;
    const int m0 = blockIdx.y * 128;
    const int n0 = blockIdx.x * 128;
    const int r = tid >> 2, c4 = (tid & 3) * 4;

    float c[4][4][4];
#pragma unroll
    for (int i = 0; i < 4; i++)
#pragma unroll
        for (int j = 0; j < 4; j++)
#pragma unroll
            for (int q = 0; q < 4; q++) c[i][j][q] = 0.f;

    for (int k0 = 0; k0 < 1024; k0 += 16) {
        float4 a0 = *(const float4*)(g_oh + (size_t)(m0 + r)      * 1024 + k0 + c4);
        float4 a1 = *(const float4*)(g_oh + (size_t)(m0 + r + 64) * 1024 + k0 + c4);
        float4 b0 = *(const float4*)(W    + (size_t)(n0 + r)      * 1024 + k0 + c4);
        float4 b1 = *(const float4*)(W    + (size_t)(n0 + r + 64) * 1024 + k0 + c4);
        __syncthreads();
        stage4(A2, c4, r, a0);  stage4(A2, c4, r + 64, a1);
        stage4(B2, c4, r, b0);  stage4(B2, c4, r + 64, b1);
        __syncthreads();
        mma_step(A2, B2, 0, wm, wn, g, t4, c);
        mma_step(A2, B2, 8, wm, wn, g, t4, c);
    }

#pragma unroll
    for (int i = 0; i < 4; i++) {
        const int gi0 = m0 + wm*64 + i*16 + g;
        const int gi1 = gi0 + 8;
#pragma unroll
        for (int j = 0; j < 4; j++) {
            const int col = n0 + wn*32 + j*8 + 2*t4;
            *(float2*)(Cout + (size_t)gi0 * 1024 + col) = make_float2(c[i][j][0], c[i][j][1]);
            *(float2*)(Cout + (size_t)gi1 * 1024 + col) = make_float2(c[i][j][2], c[i][j][3]);
        }
    }
}

// ---------------------------------------------------------------------------
// K6: deterministic scalar finalize
// ---------------------------------------------------------------------------
__global__ void k_finalize(float* __restrict__ scal) {
    if (threadIdx.x == 0 && blockIdx.x == 0) {
        double rep = 0.0;
        for (int i = 0; i < TT; i++) rep += (double)g_repp[i];
        double de = 0.0, fe = 0.0;
        for (int i = 0; i < 256; i++) { de += (double)g_edp[i]; fe += (double)g_efp[i]; }
        const double nrows = (double)BB * HH * TT;
        scal[0] = (float)(de / nrows);
        scal[1] = (float)(-fe / nrows);
        scal[2] = (float)(rep / ((double)TT * TT - TT));
    }
}

// ---------------------------------------------------------------------------
extern "C" void kernel_launch(void* const* d_in, const int* in_sizes, int n_in,
                              void* d_out, int out_size) {
    const float* x      = (const float*)d_in[0];
    const float* qkv_w  = (const float*)d_in[1];
    const float* proj_w = (const float*)d_in[2];
    const float* pos    = (const float*)d_in[3];
    float* out   = (float*)d_out;
    float* attn  = out + ATTN_OFF;
    float* dists = out + DIST_OFF;

    k_qkv<<<dim3(24, 32), 256>>>(x, qkv_w);
    k_dists<<<TT, 256>>>(pos, dists);
    k_logits<<<dim3(136, 32), 256>>>();
    k_rowstats<<<256, 256>>>();
    k_softmax_av<<<dim3(32, 32), 256>>>(attn);
    k_proj<<<dim3(8, 32), 256>>>(proj_w, out);
    k_finalize<<<1, 32>>>(out + SCAL_OFF);
}

// round 6
// speedup vs baseline: 1.0056x; 1.0056x over previous
#include <cuda_runtime.h>
#include <cstdint>

// Problem constants
#define BB 2
#define TT 2048
#define CC 1024
#define HH 16
#define DH 64
#define BH (BB*HH)   // 32

// Output layout (tuple flattened): out, dist_energy, flop_energy, repulsion, attn, dists
#define OUT_OFF   0
#define SCAL_OFF  4194304
#define ATTN_OFF  4194307ull      // ≡3 mod 4 → attn region only 4B-aligned
#define DIST_OFF  138412035ull    // ≡3 mod 4 → dists region only 4B-aligned

#define NEGINF (-__int_as_float(0x7f800000))

// Scratch (static device memory — all 16B-aligned)
__device__ float g_q[BH * TT * DH];
__device__ float g_k[BH * TT * DH];
__device__ float g_v[BH * TT * DH];
__device__ float g_oh[BB * TT * CC];         // head outputs in [B,T,C] layout
__device__ float g_d [TT * TT];              // aligned dists copy
__device__ float g_l [(size_t)BH * TT * TT]; // staged e = exp(v - m_tile), lower tiles only
__device__ float g_repp[TT];
// per-(row, 128-tile) partials: [bh][t][tile]
__device__ float g_mp[BH * TT * 16];
__device__ float g_s1[BH * TT * 16];
__device__ float g_s2[BH * TT * 16];
__device__ float g_s3[BH * TT * 16];
__device__ float g_edp[1024];
__device__ float g_efp[1024];

// ---------------------------------------------------------------------------
// FMA-pipe exp (no MUFU): exp(x) for x <= 0 (finite), rel err ~1e-8
// ---------------------------------------------------------------------------
__device__ __forceinline__ float fexp(float x) {
    float t = fmaxf(x * 1.4426950408889634f, -126.f);
    float fi = floorf(t);
    float f = t - fi;
    float p = 1.535336188319500e-4f;
    p = fmaf(p, f, 1.339887440266574e-3f);
    p = fmaf(p, f, 9.618437357674640e-3f);
    p = fmaf(p, f, 5.550332471162809e-2f);
    p = fmaf(p, f, 2.402264791363012e-1f);
    p = fmaf(p, f, 6.931472028550421e-1f);
    p = fmaf(p, f, 1.0f);
    return __uint_as_float(__float_as_uint(p) + ((int)fi << 23));
}

// ---------------------------------------------------------------------------
// K1: QKV = X @ W^T  (M=4096, N=3072, K=1024) SIMT, routed into q/k/v
// ---------------------------------------------------------------------------
__global__ __launch_bounds__(256) void k_qkv(const float* __restrict__ X,
                                             const float* __restrict__ W) {
    __shared__ float As[16][132];
    __shared__ float Bs[16][132];
    const int tid = threadIdx.x;
    const int m0 = blockIdx.y * 128;
    const int n0 = blockIdx.x * 128;
    const int which = blockIdx.x >> 3;          // 0:q 1:k 2:v
    float* dst = (which == 0) ? g_q : (which == 1) ? g_k : g_v;
    const int r  = tid >> 2;
    const int c4 = (tid & 3) * 4;
    const int ty = tid >> 4;
    const int tx = tid & 15;

    float acc[8][8];
#pragma unroll
    for (int i = 0; i < 8; i++)
#pragma unroll
        for (int j = 0; j < 8; j++) acc[i][j] = 0.f;

    for (int k0 = 0; k0 < 1024; k0 += 16) {
        float4 a0 = *(const float4*)(X + (size_t)(m0 + r)      * 1024 + k0 + c4);
        float4 a1 = *(const float4*)(X + (size_t)(m0 + r + 64) * 1024 + k0 + c4);
        float4 b0 = *(const float4*)(W + (size_t)(n0 + r)      * 1024 + k0 + c4);
        float4 b1 = *(const float4*)(W + (size_t)(n0 + r + 64) * 1024 + k0 + c4);
        __syncthreads();
        As[c4+0][r] = a0.x; As[c4+1][r] = a0.y; As[c4+2][r] = a0.z; As[c4+3][r] = a0.w;
        As[c4+0][r+64] = a1.x; As[c4+1][r+64] = a1.y; As[c4+2][r+64] = a1.z; As[c4+3][r+64] = a1.w;
        Bs[c4+0][r] = b0.x; Bs[c4+1][r] = b0.y; Bs[c4+2][r] = b0.z; Bs[c4+3][r] = b0.w;
        Bs[c4+0][r+64] = b1.x; Bs[c4+1][r+64] = b1.y; Bs[c4+2][r+64] = b1.z; Bs[c4+3][r+64] = b1.w;
        __syncthreads();
#pragma unroll
        for (int kk = 0; kk < 16; kk++) {
            float ra[8], rb[8];
#pragma unroll
            for (int i = 0; i < 8; i++) { ra[i] = As[kk][ty*8 + i]; rb[i] = Bs[kk][tx*8 + i]; }
#pragma unroll
            for (int i = 0; i < 8; i++)
#pragma unroll
                for (int j = 0; j < 8; j++)
                    acc[i][j] += ra[i] * rb[j];
        }
    }

#pragma unroll
    for (int i = 0; i < 8; i++) {
        int gi = m0 + ty*8 + i;
        int b = gi >> 11, t = gi & 2047;
        int gj0 = n0 + tx*8;
        int c = gj0 & 1023;
        int h = c >> 6, d = c & 63;
        float* p = dst + ((size_t)((b << 4) + h) * TT + t) * DH + d;
        *(float4*)p       = make_float4(acc[i][0], acc[i][1], acc[i][2], acc[i][3]);
        *(float4*)(p + 4) = make_float4(acc[i][4], acc[i][5], acc[i][6], acc[i][7]);
    }
}

// ---------------------------------------------------------------------------
// K2: pairwise dists (grad-safe) + repulsion partials
// ---------------------------------------------------------------------------
__global__ __launch_bounds__(256) void k_dists(const float* __restrict__ pos,
                                               float* __restrict__ Dd) {
    __shared__ float sm[256];
    const int t = blockIdx.x;
    const float px = pos[t*3+0], py = pos[t*3+1], pz = pos[t*3+2];
    float rep = 0.f;
    for (int s = threadIdx.x; s < TT; s += 256) {
        float dx = px - pos[s*3+0];
        float dy = py - pos[s*3+1];
        float dz = pz - pos[s*3+2];
        float sq = dx*dx + dy*dy + dz*dz;
        float d = (sq > 0.f) ? sqrtf(sq) : 0.f;
        Dd[(size_t)t * TT + s] = d;   // scalar: output region only 4B-aligned
        g_d[(size_t)t * TT + s] = d;
        if (s != t) rep += 1.f / (d + 1e-4f);
    }
    sm[threadIdx.x] = rep;
    __syncthreads();
    for (int s = 128; s; s >>= 1) {
        if (threadIdx.x < s) sm[threadIdx.x] += sm[threadIdx.x + s];
        __syncthreads();
    }
    if (threadIdx.x == 0) g_repp[t] = sm[0];
}

// ---------------------------------------------------------------------------
// K3: logits = q@k^T/8 - dist (SIMT GEMM), fused tile-softmax:
// stores e = fexp(v - m_tile) into g_l, emits per-(row,tile) partials
// m, S1=Σe, S2=Σe·(v-m_tile), S3=Σe·d.  Lower-triangle tiles only.
// ---------------------------------------------------------------------------
__global__ __launch_bounds__(256) void k_logits() {
    const int bh = blockIdx.y;
    const int p  = blockIdx.x;             // 0..135 triangular tile index
    int it = (int)((sqrtf(8.f * p + 1.f) - 1.f) * 0.5f);
    while ((it + 1) * (it + 2) / 2 <= p) it++;
    while (it * (it + 1) / 2 > p) it--;
    const int jt = p - it * (it + 1) / 2;
    const int m0 = it * 128;
    const int n0 = jt * 128;

    float* Lp = g_l + (size_t)bh * TT * TT;
    const float* Q  = g_q + (size_t)bh * TT * DH;
    const float* Kp = g_k + (size_t)bh * TT * DH;

    __shared__ float As[16][132];
    __shared__ float Bs[16][132];
    __shared__ float red1[128][17];
    __shared__ float red2[128][17];
    __shared__ float red3[128][17];
    __shared__ float rowm[128];

    const int tid = threadIdx.x;
    const int ty = tid >> 4, tx = tid & 15;
    const int r = tid >> 2, c4 = (tid & 3) * 4;

    float acc[8][8];
#pragma unroll
    for (int i = 0; i < 8; i++)
#pragma unroll
        for (int j = 0; j < 8; j++) acc[i][j] = 0.f;

#pragma unroll
    for (int k0 = 0; k0 < 64; k0 += 16) {
        float4 a0 = *(const float4*)(Q  + (size_t)(m0 + r)      * DH + k0 + c4);
        float4 a1 = *(const float4*)(Q  + (size_t)(m0 + r + 64) * DH + k0 + c4);
        float4 b0 = *(const float4*)(Kp + (size_t)(n0 + r)      * DH + k0 + c4);
        float4 b1 = *(const float4*)(Kp + (size_t)(n0 + r + 64) * DH + k0 + c4);
        __syncthreads();
        As[c4+0][r] = a0.x; As[c4+1][r] = a0.y; As[c4+2][r] = a0.z; As[c4+3][r] = a0.w;
        As[c4+0][r+64] = a1.x; As[c4+1][r+64] = a1.y; As[c4+2][r+64] = a1.z; As[c4+3][r+64] = a1.w;
        Bs[c4+0][r] = b0.x; Bs[c4+1][r] = b0.y; Bs[c4+2][r] = b0.z; Bs[c4+3][r] = b0.w;
        Bs[c4+0][r+64] = b1.x; Bs[c4+1][r+64] = b1.y; Bs[c4+2][r+64] = b1.z; Bs[c4+3][r+64] = b1.w;
        __syncthreads();
#pragma unroll
        for (int kk = 0; kk < 16; kk++) {
            float ra[8], rb[8];
#pragma unroll
            for (int i = 0; i < 8; i++) { ra[i] = As[kk][ty*8 + i]; rb[i] = Bs[kk][tx*8 + i]; }
#pragma unroll
            for (int i = 0; i < 8; i++)
#pragma unroll
                for (int j = 0; j < 8; j++)
                    acc[i][j] += ra[i] * rb[j];
        }
    }

    // ---- Phase 1: v = qk/8 - d (mask -> NEGINF), per-row tile max ----
#pragma unroll
    for (int i = 0; i < 8; i++) {
        const int t = m0 + ty*8 + i;
        const int s0 = n0 + tx*8;
        const float4 d0 = *(const float4*)(g_d + (size_t)t * TT + s0);
        const float4 d1 = *(const float4*)(g_d + (size_t)t * TT + s0 + 4);
        float v[8];
        v[0] = acc[i][0]*0.125f - d0.x; v[1] = acc[i][1]*0.125f - d0.y;
        v[2] = acc[i][2]*0.125f - d0.z; v[3] = acc[i][3]*0.125f - d0.w;
        v[4] = acc[i][4]*0.125f - d1.x; v[5] = acc[i][5]*0.125f - d1.y;
        v[6] = acc[i][6]*0.125f - d1.z; v[7] = acc[i][7]*0.125f - d1.w;
#pragma unroll
        for (int j = 0; j < 8; j++) if (s0 + j > t) v[j] = NEGINF;
#pragma unroll
        for (int j = 0; j < 8; j++) acc[i][j] = v[j];
        float mx = v[0];
#pragma unroll
        for (int j = 1; j < 8; j++) mx = fmaxf(mx, v[j]);
        red1[ty*8 + i][tx] = mx;
    }
    __syncthreads();
    if (tid < 128) {
        float m = red1[tid][0];
#pragma unroll
        for (int c = 1; c < 16; c++) m = fmaxf(m, red1[tid][c]);
        rowm[tid] = m;
    }
    __syncthreads();

    // ---- Phase 2: e = fexp(v - m_tile), store, partials S1/S2/S3 ----
#pragma unroll
    for (int i = 0; i < 8; i++) {
        const int t = m0 + ty*8 + i;
        const int s0 = n0 + tx*8;
        const float m = rowm[ty*8 + i];
        const float4 d0 = *(const float4*)(g_d + (size_t)t * TT + s0);
        const float4 d1 = *(const float4*)(g_d + (size_t)t * TT + s0 + 4);
        float dv[8] = {d0.x, d0.y, d0.z, d0.w, d1.x, d1.y, d1.z, d1.w};
        float e[8];
        float rs1 = 0.f, rs2 = 0.f, rs3 = 0.f;
#pragma unroll
        for (int j = 0; j < 8; j++) {
            if (s0 + j <= t) {
                const float xm = acc[i][j] - m;
                const float ee = fexp(xm);
                e[j] = ee;
                rs1 += ee;
                rs2 += ee * xm;
                rs3 += ee * dv[j];
            } else e[j] = 0.f;
        }
        float* lp = Lp + (size_t)t * TT + s0;
        *(float4*)lp       = make_float4(e[0], e[1], e[2], e[3]);
        *(float4*)(lp + 4) = make_float4(e[4], e[5], e[6], e[7]);
        red1[ty*8 + i][tx] = rs1;
        red2[ty*8 + i][tx] = rs2;
        red3[ty*8 + i][tx] = rs3;
    }
    __syncthreads();
    if (tid < 128) {
        float l1 = 0.f, l2 = 0.f, l3 = 0.f;
#pragma unroll
        for (int c = 0; c < 16; c++) { l1 += red1[tid][c]; l2 += red2[tid][c]; l3 += red3[tid][c]; }
        const size_t ix = ((size_t)bh * TT + m0 + tid) * 16 + jt;
        g_mp[ix] = rowm[tid];
        g_s1[ix] = l1;
        g_s2[ix] = l2;
        g_s3[ix] = l3;
    }
}

// ---------------------------------------------------------------------------
// K4: row stats (folded) + p = e*C (attn write) + energies + O = P@V
// block: (row-tile of 64, bh). 256 threads. Heavy blocks scheduled first.
// ---------------------------------------------------------------------------
__global__ __launch_bounds__(256) void k_softmax_av(float* __restrict__ attn) {
    const int bh = blockIdx.y;
    const int t0 = (int)(gridDim.x - 1 - blockIdx.x) * 64;  // heavy first
    const int b = bh >> 4, h = bh & 15;
    const float* L = g_l + (size_t)bh * TT * TT;
    float* A = attn + (size_t)bh * TT * TT;
    const float* V = g_v + (size_t)bh * TT * DH;

    __shared__ float Cs2[64][16];
    __shared__ float Ps[64][68];
    __shared__ float Vs[64][68];
    __shared__ float sredA[64];
    __shared__ float sredB[64];

    const int tid = threadIdx.x;
    const int ty = tid >> 4, tx = tid & 15;
    const int ntile = (t0 >> 7) + 1;

    // ---- Prologue: per-row combine of tile partials + energies ----
    if (tid < 64) {
        const size_t base = ((size_t)bh * TT + t0 + tid) * 16;
        float m = NEGINF;
        for (int j = 0; j < ntile; j++) m = fmaxf(m, g_mp[base + j]);
        float l = 0.f;
        for (int j = 0; j < ntile; j++) l += g_s1[base + j] * fexp(g_mp[base + j] - m);
        const float li = 1.f / l;
        const float ll = __logf(l);
        float ed = 0.f, ef = 0.f;
        for (int j = 0; j < ntile; j++) {
            const float dm = g_mp[base + j] - m;
            const float C = fexp(dm) * li;
            Cs2[tid][j] = C;
            ed += C * g_s3[base + j];
            ef += C * (g_s2[base + j] + (dm - ll) * g_s1[base + j]);
        }
        sredA[tid] = ed;
        sredB[tid] = ef;
    }
    __syncthreads();
    for (int s = 32; s; s >>= 1) {
        if (tid < s) { sredA[tid] += sredA[tid + s]; sredB[tid] += sredB[tid + s]; }
        __syncthreads();
    }
    if (tid == 0) {
        const int bid = blockIdx.y * 32 + blockIdx.x;
        g_edp[bid] = sredA[0];
        g_efp[bid] = sredB[0];
    }

    // ---- Main: p = e*C, attn write, P@V ----
    float acc[4][4];
#pragma unroll
    for (int i = 0; i < 4; i++)
#pragma unroll
        for (int j = 0; j < 4; j++) acc[i][j] = 0.f;

    const int nt = t0 + 64;
    for (int s0 = 0; s0 < nt; s0 += 64) {
        __syncthreads();
        const int jt = s0 >> 7;
#pragma unroll 4
        for (int e = tid; e < 1024; e += 256) {
            const int rl = e >> 4, cidx = (e & 15) * 4;
            const size_t gix = (size_t)(t0 + rl) * TT + s0 + cidx;
            float4 e4 = *(const float4*)(L + gix);
            const float Cc = Cs2[rl][jt];
            float4 p4 = make_float4(e4.x * Cc, e4.y * Cc, e4.z * Cc, e4.w * Cc);
            A[gix]     = p4.x;    // scalar stores: attn region only 4B-aligned
            A[gix + 1] = p4.y;
            A[gix + 2] = p4.z;
            A[gix + 3] = p4.w;
            *(float4*)&Ps[rl][cidx] = p4;
        }
#pragma unroll 4
        for (int e = tid; e < 1024; e += 256) {
            const int ss = e >> 4, d = (e & 15) * 4;
            *(float4*)&Vs[ss][d] = *(const float4*)(V + (size_t)(s0 + ss) * DH + d);
        }
        __syncthreads();
#pragma unroll 4
        for (int ss = 0; ss < 64; ss++) {
            float4 v4 = *(const float4*)&Vs[ss][tx * 4];
            float p0 = Ps[ty*4+0][ss];
            float p1 = Ps[ty*4+1][ss];
            float p2 = Ps[ty*4+2][ss];
            float p3 = Ps[ty*4+3][ss];
            acc[0][0] += p0*v4.x; acc[0][1] += p0*v4.y; acc[0][2] += p0*v4.z; acc[0][3] += p0*v4.w;
            acc[1][0] += p1*v4.x; acc[1][1] += p1*v4.y; acc[1][2] += p1*v4.z; acc[1][3] += p1*v4.w;
            acc[2][0] += p2*v4.x; acc[2][1] += p2*v4.y; acc[2][2] += p2*v4.z; acc[2][3] += p2*v4.w;
            acc[3][0] += p3*v4.x; acc[3][1] += p3*v4.y; acc[3][2] += p3*v4.z; acc[3][3] += p3*v4.w;
        }
    }

    // zero-fill fully-masked attn region (scalar coalesced)
    if (nt < TT) {
        const int nrem = TT - nt;
        for (int q = tid; q < 64 * nrem; q += 256) {
            const int rl = q / nrem;
            const int s  = q - rl * nrem;
            A[(size_t)(t0 + rl) * TT + nt + s] = 0.f;
        }
    }

#pragma unroll
    for (int i = 0; i < 4; i++) {
        const size_t row = (size_t)(b * TT + t0 + ty*4 + i) * CC + h * DH + tx * 4;
        *(float4*)(g_oh + row) = make_float4(acc[i][0], acc[i][1], acc[i][2], acc[i][3]);
    }
}

// ---------------------------------------------------------------------------
// K5: out = g_oh @ proj_w^T  (M=4096, N=1024, K=1024) SIMT
// ---------------------------------------------------------------------------
__global__ __launch_bounds__(256) void k_proj(const float* __restrict__ W,
                                              float* __restrict__ Cout) {
    __shared__ float As[16][132];
    __shared__ float Bs[16][132];
    const int tid = threadIdx.x;
    const int m0 = blockIdx.y * 128;
    const int n0 = blockIdx.x * 128;
    const int r  = tid >> 2;
    const int c4 = (tid & 3) * 4;
    const int ty = tid >> 4;
    const int tx = tid & 15;

    float acc[8][8];
#pragma unroll
    for (int i = 0; i < 8; i++)
#pragma unroll
        for (int j = 0; j < 8; j++) acc[i][j] = 0.f;

    for (int k0 = 0; k0 < 1024; k0 += 16) {
        float4 a0 = *(const float4*)(g_oh + (size_t)(m0 + r)      * 1024 + k0 + c4);
        float4 a1 = *(const float4*)(g_oh + (size_t)(m0 + r + 64) * 1024 + k0 + c4);
        float4 b0 = *(const float4*)(W    + (size_t)(n0 + r)      * 1024 + k0 + c4);
        float4 b1 = *(const float4*)(W    + (size_t)(n0 + r + 64) * 1024 + k0 + c4);
        __syncthreads();
        As[c4+0][r] = a0.x; As[c4+1][r] = a0.y; As[c4+2][r] = a0.z; As[c4+3][r] = a0.w;
        As[c4+0][r+64] = a1.x; As[c4+1][r+64] = a1.y; As[c4+2][r+64] = a1.z; As[c4+3][r+64] = a1.w;
        Bs[c4+0][r] = b0.x; Bs[c4+1][r] = b0.y; Bs[c4+2][r] = b0.z; Bs[c4+3][r] = b0.w;
        Bs[c4+0][r+64] = b1.x; Bs[c4+1][r+64] = b1.y; Bs[c4+2][r+64] = b1.z; Bs[c4+3][r+64] = b1.w;
        __syncthreads();
#pragma unroll
        for (int kk = 0; kk < 16; kk++) {
            float ra[8], rb[8];
#pragma unroll
            for (int i = 0; i < 8; i++) { ra[i] = As[kk][ty*8 + i]; rb[i] = Bs[kk][tx*8 + i]; }
#pragma unroll
            for (int i = 0; i < 8; i++)
#pragma unroll
                for (int j = 0; j < 8; j++)
                    acc[i][j] += ra[i] * rb[j];
        }
    }

#pragma unroll
    for (int i = 0; i < 8; i++) {
        float* base = Cout + (size_t)(m0 + ty*8 + i) * 1024 + n0 + tx*8;
        *(float4*)base       = make_float4(acc[i][0], acc[i][1], acc[i][2], acc[i][3]);
        *(float4*)(base + 4) = make_float4(acc[i][4], acc[i][5], acc[i][6], acc[i][7]);
    }
}

// ---------------------------------------------------------------------------
// K6: deterministic scalar finalize
// ---------------------------------------------------------------------------
__global__ void k_finalize(float* __restrict__ scal) {
    if (threadIdx.x == 0 && blockIdx.x == 0) {
        double rep = 0.0;
        for (int i = 0; i < TT; i++) rep += (double)g_repp[i];
        double de = 0.0, fe = 0.0;
        for (int i = 0; i < 1024; i++) { de += (double)g_edp[i]; fe += (double)g_efp[i]; }
        const double nrows = (double)BB * HH * TT;
        scal[0] = (float)(de / nrows);
        scal[1] = (float)(-fe / nrows);
        scal[2] = (float)(rep / ((double)TT * TT - TT));
    }
}

// ---------------------------------------------------------------------------
extern "C" void kernel_launch(void* const* d_in, const int* in_sizes, int n_in,
                              void* d_out, int out_size) {
    const float* x      = (const float*)d_in[0];
    const float* qkv_w  = (const float*)d_in[1];
    const float* proj_w = (const float*)d_in[2];
    const float* pos    = (const float*)d_in[3];
    float* out   = (float*)d_out;
    float* attn  = out + ATTN_OFF;
    float* dists = out + DIST_OFF;

    k_qkv<<<dim3(24, 32), 256>>>(x, qkv_w);
    k_dists<<<TT, 256>>>(pos, dists);
    k_logits<<<dim3(136, 32), 256>>>();
    k_softmax_av<<<dim3(32, 32), 256>>>(attn);   // 4th launch → ncu captures this
    k_proj<<<dim3(8, 32), 256>>>(proj_w, out);
    k_finalize<<<1, 32>>>(out + SCAL_OFF);
}

// round 11
// speedup vs baseline: 1.0259x; 1.0202x over previous
#include <cuda_runtime.h>
#include <cstdint>

// Problem constants
#define BB 2
#define TT 2048
#define CC 1024
#define HH 16
#define DH 64
#define BH (BB*HH)   // 32

// Output layout: out, dist_energy, flop_energy, repulsion, attn, dists
#define OUT_OFF   0
#define SCAL_OFF  4194304
#define ATTN_OFF  4194307ull      // ≡3 mod 4 → attn region only 4B-aligned; +1 is 16B-aligned
#define DIST_OFF  138412035ull    // ≡3 mod 4

#define NEGINF (-__int_as_float(0x7f800000))

// Scratch (static device memory)
__device__ float g_q[BH * TT * DH];
__device__ float g_k[BH * TT * DH];
__device__ float g_v[BH * TT * DH];
__device__ float g_oh[BB * TT * CC];
__device__ float g_d [TT * TT];
__device__ float g_l [(size_t)BH * TT * TT];
__device__ float g_repp[TT];
__device__ float g_mp[BH * TT * 16];
__device__ float g_s1[BH * TT * 16];
__device__ float g_s2[BH * TT * 16];
__device__ float g_s3[BH * TT * 16];
__device__ float g_edp[1024];
__device__ float g_efp[1024];

// ---------------------------------------------------------------------------
// K1: QKV = X @ W^T  (M=4096, N=3072, K=1024) SIMT @ fp32 roofline
// ---------------------------------------------------------------------------
__global__ __launch_bounds__(256) void k_qkv(const float* __restrict__ X,
                                             const float* __restrict__ W) {
    __shared__ float As[16][132];
    __shared__ float Bs[16][132];
    const int tid = threadIdx.x;
    const int m0 = blockIdx.y * 128;
    const int n0 = blockIdx.x * 128;
    const int which = blockIdx.x >> 3;
    float* dst = (which == 0) ? g_q : (which == 1) ? g_k : g_v;
    const int r  = tid >> 2;
    const int c4 = (tid & 3) * 4;
    const int ty = tid >> 4;
    const int tx = tid & 15;

    float acc[8][8];
#pragma unroll
    for (int i = 0; i < 8; i++)
#pragma unroll
        for (int j = 0; j < 8; j++) acc[i][j] = 0.f;

    for (int k0 = 0; k0 < 1024; k0 += 16) {
        float4 a0 = *(const float4*)(X + (size_t)(m0 + r)      * 1024 + k0 + c4);
        float4 a1 = *(const float4*)(X + (size_t)(m0 + r + 64) * 1024 + k0 + c4);
        float4 b0 = *(const float4*)(W + (size_t)(n0 + r)      * 1024 + k0 + c4);
        float4 b1 = *(const float4*)(W + (size_t)(n0 + r + 64) * 1024 + k0 + c4);
        __syncthreads();
        As[c4+0][r] = a0.x; As[c4+1][r] = a0.y; As[c4+2][r] = a0.z; As[c4+3][r] = a0.w;
        As[c4+0][r+64] = a1.x; As[c4+1][r+64] = a1.y; As[c4+2][r+64] = a1.z; As[c4+3][r+64] = a1.w;
        Bs[c4+0][r] = b0.x; Bs[c4+1][r] = b0.y; Bs[c4+2][r] = b0.z; Bs[c4+3][r] = b0.w;
        Bs[c4+0][r+64] = b1.x; Bs[c4+1][r+64] = b1.y; Bs[c4+2][r+64] = b1.z; Bs[c4+3][r+64] = b1.w;
        __syncthreads();
#pragma unroll
        for (int kk = 0; kk < 16; kk++) {
            float ra[8], rb[8];
#pragma unroll
            for (int i = 0; i < 8; i++) { ra[i] = As[kk][ty*8 + i]; rb[i] = Bs[kk][tx*8 + i]; }
#pragma unroll
            for (int i = 0; i < 8; i++)
#pragma unroll
                for (int j = 0; j < 8; j++)
                    acc[i][j] += ra[i] * rb[j];
        }
    }

#pragma unroll
    for (int i = 0; i < 8; i++) {
        int gi = m0 + ty*8 + i;
        int b = gi >> 11, t = gi & 2047;
        int gj0 = n0 + tx*8;
        int c = gj0 & 1023;
        int h = c >> 6, d = c & 63;
        float* p = dst + ((size_t)((b << 4) + h) * TT + t) * DH + d;
        *(float4*)p       = make_float4(acc[i][0], acc[i][1], acc[i][2], acc[i][3]);
        *(float4*)(p + 4) = make_float4(acc[i][4], acc[i][5], acc[i][6], acc[i][7]);
    }
}

// ---------------------------------------------------------------------------
// K2: pairwise dists (grad-safe) + repulsion partials
// ---------------------------------------------------------------------------
__global__ __launch_bounds__(256) void k_dists(const float* __restrict__ pos,
                                               float* __restrict__ Dd) {
    __shared__ float sm[256];
    const int t = blockIdx.x;
    const float px = pos[t*3+0], py = pos[t*3+1], pz = pos[t*3+2];
    float rep = 0.f;
    for (int s = threadIdx.x; s < TT; s += 256) {
        float dx = px - pos[s*3+0];
        float dy = py - pos[s*3+1];
        float dz = pz - pos[s*3+2];
        float sq = dx*dx + dy*dy + dz*dz;
        float d = (sq > 0.f) ? sqrtf(sq) : 0.f;
        Dd[(size_t)t * TT + s] = d;
        g_d[(size_t)t * TT + s] = d;
        if (s != t) rep += 1.f / (d + 1e-4f);
    }
    sm[threadIdx.x] = rep;
    __syncthreads();
    for (int s = 128; s; s >>= 1) {
        if (threadIdx.x < s) sm[threadIdx.x] += sm[threadIdx.x + s];
        __syncthreads();
    }
    if (threadIdx.x == 0) g_repp[t] = sm[0];
}

// tiny spacer so k_logits is the 4th launch (ncu captures launch #4)
__global__ void k_noop() {}

// ---------------------------------------------------------------------------
// K3: logits GEMM (SIMT) + fused tile-softmax partials  [profiled this round]
// ---------------------------------------------------------------------------
__global__ __launch_bounds__(256) void k_logits() {
    const int bh = blockIdx.y;
    const int p  = blockIdx.x;
    int it = (int)((sqrtf(8.f * p + 1.f) - 1.f) * 0.5f);
    while ((it + 1) * (it + 2) / 2 <= p) it++;
    while (it * (it + 1) / 2 > p) it--;
    const int jt = p - it * (it + 1) / 2;
    const int m0 = it * 128;
    const int n0 = jt * 128;

    float* Lp = g_l + (size_t)bh * TT * TT;
    const float* Q  = g_q + (size_t)bh * TT * DH;
    const float* Kp = g_k + (size_t)bh * TT * DH;

    __shared__ float As[16][132];
    __shared__ float Bs[16][132];
    __shared__ float red1[128][17];
    __shared__ float red2[128][17];
    __shared__ float red3[128][17];
    __shared__ float rowm[128];

    const int tid = threadIdx.x;
    const int ty = tid >> 4, tx = tid & 15;
    const int r = tid >> 2, c4 = (tid & 3) * 4;

    float acc[8][8];
#pragma unroll
    for (int i = 0; i < 8; i++)
#pragma unroll
        for (int j = 0; j < 8; j++) acc[i][j] = 0.f;

#pragma unroll
    for (int k0 = 0; k0 < 64; k0 += 16) {
        float4 a0 = *(const float4*)(Q  + (size_t)(m0 + r)      * DH + k0 + c4);
        float4 a1 = *(const float4*)(Q  + (size_t)(m0 + r + 64) * DH + k0 + c4);
        float4 b0 = *(const float4*)(Kp + (size_t)(n0 + r)      * DH + k0 + c4);
        float4 b1 = *(const float4*)(Kp + (size_t)(n0 + r + 64) * DH + k0 + c4);
        __syncthreads();
        As[c4+0][r] = a0.x; As[c4+1][r] = a0.y; As[c4+2][r] = a0.z; As[c4+3][r] = a0.w;
        As[c4+0][r+64] = a1.x; As[c4+1][r+64] = a1.y; As[c4+2][r+64] = a1.z; As[c4+3][r+64] = a1.w;
        Bs[c4+0][r] = b0.x; Bs[c4+1][r] = b0.y; Bs[c4+2][r] = b0.z; Bs[c4+3][r] = b0.w;
        Bs[c4+0][r+64] = b1.x; Bs[c4+1][r+64] = b1.y; Bs[c4+2][r+64] = b1.z; Bs[c4+3][r+64] = b1.w;
        __syncthreads();
#pragma unroll
        for (int kk = 0; kk < 16; kk++) {
            float ra[8], rb[8];
#pragma unroll
            for (int i = 0; i < 8; i++) { ra[i] = As[kk][ty*8 + i]; rb[i] = Bs[kk][tx*8 + i]; }
#pragma unroll
            for (int i = 0; i < 8; i++)
#pragma unroll
                for (int j = 0; j < 8; j++)
                    acc[i][j] += ra[i] * rb[j];
        }
    }

#pragma unroll
    for (int i = 0; i < 8; i++) {
        const int t = m0 + ty*8 + i;
        const int s0 = n0 + tx*8;
        const float4 d0 = *(const float4*)(g_d + (size_t)t * TT + s0);
        const float4 d1 = *(const float4*)(g_d + (size_t)t * TT + s0 + 4);
        float v[8];
        v[0] = acc[i][0]*0.125f - d0.x; v[1] = acc[i][1]*0.125f - d0.y;
        v[2] = acc[i][2]*0.125f - d0.z; v[3] = acc[i][3]*0.125f - d0.w;
        v[4] = acc[i][4]*0.125f - d1.x; v[5] = acc[i][5]*0.125f - d1.y;
        v[6] = acc[i][6]*0.125f - d1.z; v[7] = acc[i][7]*0.125f - d1.w;
#pragma unroll
        for (int j = 0; j < 8; j++) if (s0 + j > t) v[j] = NEGINF;
#pragma unroll
        for (int j = 0; j < 8; j++) acc[i][j] = v[j];
        float mx = v[0];
#pragma unroll
        for (int j = 1; j < 8; j++) mx = fmaxf(mx, v[j]);
        red1[ty*8 + i][tx] = mx;
    }
    __syncthreads();
    if (tid < 128) {
        float m = red1[tid][0];
#pragma unroll
        for (int c2 = 1; c2 < 16; c2++) m = fmaxf(m, red1[tid][c2]);
        rowm[tid] = m;
    }
    __syncthreads();

#pragma unroll
    for (int i = 0; i < 8; i++) {
        const int t = m0 + ty*8 + i;
        const int s0 = n0 + tx*8;
        const float m = rowm[ty*8 + i];
        const float4 d0 = *(const float4*)(g_d + (size_t)t * TT + s0);
        const float4 d1 = *(const float4*)(g_d + (size_t)t * TT + s0 + 4);
        float dv[8] = {d0.x, d0.y, d0.z, d0.w, d1.x, d1.y, d1.z, d1.w};
        float e[8];
        float rs1 = 0.f, rs2 = 0.f, rs3 = 0.f;
#pragma unroll
        for (int j = 0; j < 8; j++) {
            if (s0 + j <= t) {
                const float xm = acc[i][j] - m;
                const float ee = __expf(xm);
                e[j] = ee;
                rs1 += ee;
                rs2 += ee * xm;
                rs3 += ee * dv[j];
            } else e[j] = 0.f;
        }
        float* lp = Lp + (size_t)t * TT + s0;
        *(float4*)lp       = make_float4(e[0], e[1], e[2], e[3]);
        *(float4*)(lp + 4) = make_float4(e[4], e[5], e[6], e[7]);
        red1[ty*8 + i][tx] = rs1;
        red2[ty*8 + i][tx] = rs2;
        red3[ty*8 + i][tx] = rs3;
    }
    __syncthreads();
    if (tid < 128) {
        float l1 = 0.f, l2 = 0.f, l3 = 0.f;
#pragma unroll
        for (int c2 = 0; c2 < 16; c2++) { l1 += red1[tid][c2]; l2 += red2[tid][c2]; l3 += red3[tid][c2]; }
        const size_t ix = ((size_t)bh * TT + m0 + tid) * 16 + jt;
        g_mp[ix] = rowm[tid];
        g_s1[ix] = l1;
        g_s2[ix] = l2;
        g_s3[ix] = l3;
    }
}

// ---------------------------------------------------------------------------
// K4: row stats + p = e*C (SHIFTED vector attn stores) + energies + P@V
//     (float4-only inner GEMM: 128 LDS.128 vs 320 mixed ops per thread/tile)
// ---------------------------------------------------------------------------
__global__ __launch_bounds__(256) void k_softmax_av(float* __restrict__ attn) {
    const int bh = blockIdx.y;
    const int t0 = (int)(gridDim.x - 1 - blockIdx.x) * 64;  // heavy first
    const int b = bh >> 4, h = bh & 15;
    const float* L = g_l + (size_t)bh * TT * TT;
    float* A = attn + (size_t)bh * TT * TT;
    const float* V = g_v + (size_t)bh * TT * DH;

    __shared__ float Cs2[64][16];
    __shared__ float Ps[64][68];
    __shared__ float Vs[64][68];
    __shared__ float sredA[64];
    __shared__ float sredB[64];

    const int tid = threadIdx.x;
    const int wid = tid >> 5, lane = tid & 31;
    const int ty = tid >> 4, tx = tid & 15;
    const int ntile = (t0 >> 7) + 1;

    // ---- Prologue: per-row stats + energies ----
    if (tid < 64) {
        const size_t base = ((size_t)bh * TT + t0 + tid) * 16;
        float m = NEGINF;
        for (int j = 0; j < ntile; j++) m = fmaxf(m, g_mp[base + j]);
        float l = 0.f;
        for (int j = 0; j < ntile; j++) l += g_s1[base + j] * __expf(g_mp[base + j] - m);
        const float li = 1.f / l;
        const float ll = __logf(l);
        float ed = 0.f, ef = 0.f;
        for (int j = 0; j < ntile; j++) {
            const float dm = g_mp[base + j] - m;
            const float C = __expf(dm) * li;
            Cs2[tid][j] = C;
            ed += C * g_s3[base + j];
            ef += C * (g_s2[base + j] + (dm - ll) * g_s1[base + j]);
        }
        sredA[tid] = ed;
        sredB[tid] = ef;
    }
    __syncthreads();
    for (int s = 32; s; s >>= 1) {
        if (tid < s) { sredA[tid] += sredA[tid + s]; sredB[tid] += sredB[tid + s]; }
        __syncthreads();
    }
    if (tid == 0) {
        const int bid = blockIdx.y * 32 + blockIdx.x;
        g_edp[bid] = sredA[0];
        g_efp[bid] = sredB[0];
    }

    float acc[4][4];
#pragma unroll
    for (int i = 0; i < 4; i++)
#pragma unroll
        for (int j = 0; j < 4; j++) acc[i][j] = 0.f;

    const int nt = t0 + 64;
    for (int s0 = 0; s0 < nt; s0 += 64) {
        __syncthreads();
        const int jt = s0 >> 7;
        // ---- P produce: 16 elems/thread; shifted vector stores to attn ----
        {
            const int rl = tid >> 2, cg = (tid & 3) * 16;
            const size_t g0 = (size_t)(t0 + rl) * TT + s0 + cg;
            const float Cc = Cs2[rl][jt];
            float pv[16];
#pragma unroll
            for (int q4 = 0; q4 < 4; q4++) {
                float4 e4 = *(const float4*)(L + g0 + q4*4);
                float4 p4 = make_float4(e4.x*Cc, e4.y*Cc, e4.z*Cc, e4.w*Cc);
                *(float4*)&Ps[rl][cg + q4*4] = p4;
                pv[q4*4+0] = p4.x; pv[q4*4+1] = p4.y;
                pv[q4*4+2] = p4.z; pv[q4*4+3] = p4.w;
            }
            // element index of A[g0] in out is ≡3 mod 4 → A+g0+1 is 16B-aligned
            A[g0] = pv[0];
            *(float4*)(A + g0 + 1)  = make_float4(pv[1],  pv[2],  pv[3],  pv[4]);
            *(float4*)(A + g0 + 5)  = make_float4(pv[5],  pv[6],  pv[7],  pv[8]);
            *(float4*)(A + g0 + 9)  = make_float4(pv[9],  pv[10], pv[11], pv[12]);
            *(float2*)(A + g0 + 13) = make_float2(pv[13], pv[14]);
            A[g0 + 15] = pv[15];
        }
        // ---- V tile ----
#pragma unroll 4
        for (int e = tid; e < 1024; e += 256) {
            const int ss = e >> 4, d = (e & 15) * 4;
            *(float4*)&Vs[ss][d] = *(const float4*)(V + (size_t)(s0 + ss) * DH + d);
        }
        __syncthreads();
        // ---- P@V: all-float4 LDS ----
#pragma unroll 4
        for (int ss4 = 0; ss4 < 16; ss4++) {
            const float4 v0 = *(const float4*)&Vs[ss4*4+0][tx*4];
            const float4 v1 = *(const float4*)&Vs[ss4*4+1][tx*4];
            const float4 v2 = *(const float4*)&Vs[ss4*4+2][tx*4];
            const float4 v3 = *(const float4*)&Vs[ss4*4+3][tx*4];
#pragma unroll
            for (int i = 0; i < 4; i++) {
                const float4 pr = *(const float4*)&Ps[ty*4+i][ss4*4];
                acc[i][0] += pr.x*v0.x + pr.y*v1.x + pr.z*v2.x + pr.w*v3.x;
                acc[i][1] += pr.x*v0.y + pr.y*v1.y + pr.z*v2.y + pr.w*v3.y;
                acc[i][2] += pr.x*v0.z + pr.y*v1.z + pr.z*v2.z + pr.w*v3.z;
                acc[i][3] += pr.x*v0.w + pr.y*v1.w + pr.z*v2.w + pr.w*v3.w;
            }
        }
    }

    // ---- vectorized zero-fill of fully-masked region (shifted) ----
    if (nt < TT) {
        const int nrem = TT - nt;
        const int n4 = (nrem - 4) >> 2;
        const float4 z4 = make_float4(0.f, 0.f, 0.f, 0.f);
        for (int rl = wid; rl < 64; rl += 8) {
            const size_t base = (size_t)(t0 + rl) * TT + nt;
            if (lane == 0) {
                A[base] = 0.f;
                A[base + 1 + 4*n4] = 0.f;
                A[base + 2 + 4*n4] = 0.f;
                A[base + 3 + 4*n4] = 0.f;
            }
            for (int i = lane; i < n4; i += 32)
                *(float4*)(A + base + 1 + 4*i) = z4;
        }
    }

    // ---- O tile to g_oh ([B,T,C]) ----
#pragma unroll
    for (int i = 0; i < 4; i++) {
        const size_t row = (size_t)(b * TT + t0 + ty*4 + i) * CC + h * DH + tx * 4;
        *(float4*)(g_oh + row) = make_float4(acc[i][0], acc[i][1], acc[i][2], acc[i][3]);
    }
}

// ---------------------------------------------------------------------------
// K5: out = g_oh @ proj_w^T  (M=4096, N=1024, K=1024) SIMT
// ---------------------------------------------------------------------------
__global__ __launch_bounds__(256) void k_proj(const float* __restrict__ W,
                                              float* __restrict__ Cout) {
    __shared__ float As[16][132];
    __shared__ float Bs[16][132];
    const int tid = threadIdx.x;
    const int m0 = blockIdx.y * 128;
    const int n0 = blockIdx.x * 128;
    const int r  = tid >> 2;
    const int c4 = (tid & 3) * 4;
    const int ty = tid >> 4;
    const int tx = tid & 15;

    float acc[8][8];
#pragma unroll
    for (int i = 0; i < 8; i++)
#pragma unroll
        for (int j = 0; j < 8; j++) acc[i][j] = 0.f;

    for (int k0 = 0; k0 < 1024; k0 += 16) {
        float4 a0 = *(const float4*)(g_oh + (size_t)(m0 + r)      * 1024 + k0 + c4);
        float4 a1 = *(const float4*)(g_oh + (size_t)(m0 + r + 64) * 1024 + k0 + c4);
        float4 b0 = *(const float4*)(W    + (size_t)(n0 + r)      * 1024 + k0 + c4);
        float4 b1 = *(const float4*)(W    + (size_t)(n0 + r + 64) * 1024 + k0 + c4);
        __syncthreads();
        As[c4+0][r] = a0.x; As[c4+1][r] = a0.y; As[c4+2][r] = a0.z; As[c4+3][r] = a0.w;
        As[c4+0][r+64] = a1.x; As[c4+1][r+64] = a1.y; As[c4+2][r+64] = a1.z; As[c4+3][r+64] = a1.w;
        Bs[c4+0][r] = b0.x; Bs[c4+1][r] = b0.y; Bs[c4+2][r] = b0.z; Bs[c4+3][r] = b0.w;
        Bs[c4+0][r+64] = b1.x; Bs[c4+1][r+64] = b1.y; Bs[c4+2][r+64] = b1.z; Bs[c4+3][r+64] = b1.w;
        __syncthreads();
#pragma unroll
        for (int kk = 0; kk < 16; kk++) {
            float ra[8], rb[8];
#pragma unroll
            for (int i = 0; i < 8; i++) { ra[i] = As[kk][ty*8 + i]; rb[i] = Bs[kk][tx*8 + i]; }
#pragma unroll
            for (int i = 0; i < 8; i++)
#pragma unroll
                for (int j = 0; j < 8; j++)
                    acc[i][j] += ra[i] * rb[j];
        }
    }

#pragma unroll
    for (int i = 0; i < 8; i++) {
        float* base = Cout + (size_t)(m0 + ty*8 + i) * 1024 + n0 + tx*8;
        *(float4*)base       = make_float4(acc[i][0], acc[i][1], acc[i][2], acc[i][3]);
        *(float4*)(base + 4) = make_float4(acc[i][4], acc[i][5], acc[i][6], acc[i][7]);
    }
}

// ---------------------------------------------------------------------------
// K6: deterministic scalar finalize
// ---------------------------------------------------------------------------
__global__ void k_finalize(float* __restrict__ scal) {
    if (threadIdx.x == 0 && blockIdx.x == 0) {
        double rep = 0.0;
        for (int i = 0; i < TT; i++) rep += (double)g_repp[i];
        double de = 0.0, fe = 0.0;
        for (int i = 0; i < 1024; i++) { de += (double)g_edp[i]; fe += (double)g_efp[i]; }
        const double nrows = (double)BB * HH * TT;
        scal[0] = (float)(de / nrows);
        scal[1] = (float)(-fe / nrows);
        scal[2] = (float)(rep / ((double)TT * TT - TT));
    }
}

// ---------------------------------------------------------------------------
extern "C" void kernel_launch(void* const* d_in, const int* in_sizes, int n_in,
                              void* d_out, int out_size) {
    const float* x      = (const float*)d_in[0];
    const float* qkv_w  = (const float*)d_in[1];
    const float* proj_w = (const float*)d_in[2];
    const float* pos    = (const float*)d_in[3];
    float* out   = (float*)d_out;
    float* attn  = out + ATTN_OFF;
    float* dists = out + DIST_OFF;

    k_qkv<<<dim3(24, 32), 256>>>(x, qkv_w);        // 1
    k_dists<<<TT, 256>>>(pos, dists);              // 2
    k_noop<<<1, 32>>>();                           // 3 (spacer)
    k_logits<<<dim3(136, 32), 256>>>();            // 4 → profiled
    k_softmax_av<<<dim3(32, 32), 256>>>(attn);     // 5
    k_proj<<<dim3(8, 32), 256>>>(proj_w, out);     // 6
    k_finalize<<<1, 32>>>(out + SCAL_OFF);         // 7
}

// round 12
// speedup vs baseline: 1.0333x; 1.0072x over previous
#include <cuda_runtime.h>
#include <cstdint>

// Problem constants
#define BB 2
#define TT 2048
#define CC 1024
#define HH 16
#define DH 64
#define BH (BB*HH)   // 32

// Output layout: out, dist_energy, flop_energy, repulsion, attn, dists
#define OUT_OFF   0
#define SCAL_OFF  4194304
#define ATTN_OFF  4194307ull      // ≡3 mod 4 → attn region only 4B-aligned; +1 is 16B-aligned
#define DIST_OFF  138412035ull    // ≡3 mod 4

#define NEGINF (-__int_as_float(0x7f800000))

// Scratch (static device memory)
__device__ float g_q[BH * TT * DH];
__device__ float g_k[BH * TT * DH];
__device__ float g_v[BH * TT * DH];
__device__ float g_oh[BB * TT * CC];
__device__ float g_d [TT * TT];
__device__ float g_l [(size_t)BH * TT * TT];
__device__ float g_repp[TT];
__device__ float g_mp[BH * TT * 16];
__device__ float g_s1[BH * TT * 16];
__device__ float g_s2[BH * TT * 16];
__device__ float g_s3[BH * TT * 16];
__device__ float g_edp[1024];
__device__ float g_efp[1024];

// vectorized fragment fetch: 2x LDS.128 per operand row
#define LOAD_FRAG8(dst, S, kk, base)                                   \
    {                                                                  \
        const float4 _v0 = *(const float4*)&S[kk][(base)];             \
        const float4 _v1 = *(const float4*)&S[kk][(base) + 4];         \
        dst[0] = _v0.x; dst[1] = _v0.y; dst[2] = _v0.z; dst[3] = _v0.w;\
        dst[4] = _v1.x; dst[5] = _v1.y; dst[6] = _v1.z; dst[7] = _v1.w;\
    }

// ---------------------------------------------------------------------------
// K1: QKV = X @ W^T  (M=4096, N=3072, K=1024) SIMT, vector LDS fragments
// ---------------------------------------------------------------------------
__global__ __launch_bounds__(256) void k_qkv(const float* __restrict__ X,
                                             const float* __restrict__ W) {
    __shared__ float As[16][132];
    __shared__ float Bs[16][132];
    const int tid = threadIdx.x;
    const int m0 = blockIdx.y * 128;
    const int n0 = blockIdx.x * 128;
    const int which = blockIdx.x >> 3;
    float* dst = (which == 0) ? g_q : (which == 1) ? g_k : g_v;
    const int r  = tid >> 2;
    const int c4 = (tid & 3) * 4;
    const int ty = tid >> 4;
    const int tx = tid & 15;

    float acc[8][8];
#pragma unroll
    for (int i = 0; i < 8; i++)
#pragma unroll
        for (int j = 0; j < 8; j++) acc[i][j] = 0.f;

    for (int k0 = 0; k0 < 1024; k0 += 16) {
        float4 a0 = *(const float4*)(X + (size_t)(m0 + r)      * 1024 + k0 + c4);
        float4 a1 = *(const float4*)(X + (size_t)(m0 + r + 64) * 1024 + k0 + c4);
        float4 b0 = *(const float4*)(W + (size_t)(n0 + r)      * 1024 + k0 + c4);
        float4 b1 = *(const float4*)(W + (size_t)(n0 + r + 64) * 1024 + k0 + c4);
        __syncthreads();
        As[c4+0][r] = a0.x; As[c4+1][r] = a0.y; As[c4+2][r] = a0.z; As[c4+3][r] = a0.w;
        As[c4+0][r+64] = a1.x; As[c4+1][r+64] = a1.y; As[c4+2][r+64] = a1.z; As[c4+3][r+64] = a1.w;
        Bs[c4+0][r] = b0.x; Bs[c4+1][r] = b0.y; Bs[c4+2][r] = b0.z; Bs[c4+3][r] = b0.w;
        Bs[c4+0][r+64] = b1.x; Bs[c4+1][r+64] = b1.y; Bs[c4+2][r+64] = b1.z; Bs[c4+3][r+64] = b1.w;
        __syncthreads();
#pragma unroll
        for (int kk = 0; kk < 16; kk++) {
            float ra[8], rb[8];
            LOAD_FRAG8(ra, As, kk, ty*8);
            LOAD_FRAG8(rb, Bs, kk, tx*8);
#pragma unroll
            for (int i = 0; i < 8; i++)
#pragma unroll
                for (int j = 0; j < 8; j++)
                    acc[i][j] += ra[i] * rb[j];
        }
    }

#pragma unroll
    for (int i = 0; i < 8; i++) {
        int gi = m0 + ty*8 + i;
        int b = gi >> 11, t = gi & 2047;
        int gj0 = n0 + tx*8;
        int c = gj0 & 1023;
        int h = c >> 6, d = c & 63;
        float* p = dst + ((size_t)((b << 4) + h) * TT + t) * DH + d;
        *(float4*)p       = make_float4(acc[i][0], acc[i][1], acc[i][2], acc[i][3]);
        *(float4*)(p + 4) = make_float4(acc[i][4], acc[i][5], acc[i][6], acc[i][7]);
    }
}

// ---------------------------------------------------------------------------
// K2: pairwise dists (grad-safe) + repulsion partials
// ---------------------------------------------------------------------------
__global__ __launch_bounds__(256) void k_dists(const float* __restrict__ pos,
                                               float* __restrict__ Dd) {
    __shared__ float sm[256];
    const int t = blockIdx.x;
    const float px = pos[t*3+0], py = pos[t*3+1], pz = pos[t*3+2];
    float rep = 0.f;
    for (int s = threadIdx.x; s < TT; s += 256) {
        float dx = px - pos[s*3+0];
        float dy = py - pos[s*3+1];
        float dz = pz - pos[s*3+2];
        float sq = dx*dx + dy*dy + dz*dz;
        float d = (sq > 0.f) ? sqrtf(sq) : 0.f;
        Dd[(size_t)t * TT + s] = d;
        g_d[(size_t)t * TT + s] = d;
        if (s != t) rep += 1.f / (d + 1e-4f);
    }
    sm[threadIdx.x] = rep;
    __syncthreads();
    for (int s = 128; s; s >>= 1) {
        if (threadIdx.x < s) sm[threadIdx.x] += sm[threadIdx.x + s];
        __syncthreads();
    }
    if (threadIdx.x == 0) g_repp[t] = sm[0];
}

// spacer so k_logits is the 4th launch (ncu captures launch #4)
__global__ void k_noop() {}

// ---------------------------------------------------------------------------
// K3: logits GEMM (SIMT, vector LDS) + fused tile-softmax partials
// ---------------------------------------------------------------------------
__global__ __launch_bounds__(256) void k_logits() {
    const int bh = blockIdx.y;
    const int p  = blockIdx.x;
    int it = (int)((sqrtf(8.f * p + 1.f) - 1.f) * 0.5f);
    while ((it + 1) * (it + 2) / 2 <= p) it++;
    while (it * (it + 1) / 2 > p) it--;
    const int jt = p - it * (it + 1) / 2;
    const int m0 = it * 128;
    const int n0 = jt * 128;

    float* Lp = g_l + (size_t)bh * TT * TT;
    const float* Q  = g_q + (size_t)bh * TT * DH;
    const float* Kp = g_k + (size_t)bh * TT * DH;

    __shared__ float As[16][132];
    __shared__ float Bs[16][132];
    __shared__ float red1[128][17];
    __shared__ float red2[128][17];
    __shared__ float red3[128][17];
    __shared__ float rowm[128];

    const int tid = threadIdx.x;
    const int ty = tid >> 4, tx = tid & 15;
    const int r = tid >> 2, c4 = (tid & 3) * 4;

    float acc[8][8];
#pragma unroll
    for (int i = 0; i < 8; i++)
#pragma unroll
        for (int j = 0; j < 8; j++) acc[i][j] = 0.f;

#pragma unroll
    for (int k0 = 0; k0 < 64; k0 += 16) {
        float4 a0 = *(const float4*)(Q  + (size_t)(m0 + r)      * DH + k0 + c4);
        float4 a1 = *(const float4*)(Q  + (size_t)(m0 + r + 64) * DH + k0 + c4);
        float4 b0 = *(const float4*)(Kp + (size_t)(n0 + r)      * DH + k0 + c4);
        float4 b1 = *(const float4*)(Kp + (size_t)(n0 + r + 64) * DH + k0 + c4);
        __syncthreads();
        As[c4+0][r] = a0.x; As[c4+1][r] = a0.y; As[c4+2][r] = a0.z; As[c4+3][r] = a0.w;
        As[c4+0][r+64] = a1.x; As[c4+1][r+64] = a1.y; As[c4+2][r+64] = a1.z; As[c4+3][r+64] = a1.w;
        Bs[c4+0][r] = b0.x; Bs[c4+1][r] = b0.y; Bs[c4+2][r] = b0.z; Bs[c4+3][r] = b0.w;
        Bs[c4+0][r+64] = b1.x; Bs[c4+1][r+64] = b1.y; Bs[c4+2][r+64] = b1.z; Bs[c4+3][r+64] = b1.w;
        __syncthreads();
#pragma unroll
        for (int kk = 0; kk < 16; kk++) {
            float ra[8], rb[8];
            LOAD_FRAG8(ra, As, kk, ty*8);
            LOAD_FRAG8(rb, Bs, kk, tx*8);
#pragma unroll
            for (int i = 0; i < 8; i++)
#pragma unroll
                for (int j = 0; j < 8; j++)
                    acc[i][j] += ra[i] * rb[j];
        }
    }

#pragma unroll
    for (int i = 0; i < 8; i++) {
        const int t = m0 + ty*8 + i;
        const int s0 = n0 + tx*8;
        const float4 d0 = *(const float4*)(g_d + (size_t)t * TT + s0);
        const float4 d1 = *(const float4*)(g_d + (size_t)t * TT + s0 + 4);
        float v[8];
        v[0] = acc[i][0]*0.125f - d0.x; v[1] = acc[i][1]*0.125f - d0.y;
        v[2] = acc[i][2]*0.125f - d0.z; v[3] = acc[i][3]*0.125f - d0.w;
        v[4] = acc[i][4]*0.125f - d1.x; v[5] = acc[i][5]*0.125f - d1.y;
        v[6] = acc[i][6]*0.125f - d1.z; v[7] = acc[i][7]*0.125f - d1.w;
#pragma unroll
        for (int j = 0; j < 8; j++) if (s0 + j > t) v[j] = NEGINF;
#pragma unroll
        for (int j = 0; j < 8; j++) acc[i][j] = v[j];
        float mx = v[0];
#pragma unroll
        for (int j = 1; j < 8; j++) mx = fmaxf(mx, v[j]);
        red1[ty*8 + i][tx] = mx;
    }
    __syncthreads();
    if (tid < 128) {
        float m = red1[tid][0];
#pragma unroll
        for (int c2 = 1; c2 < 16; c2++) m = fmaxf(m, red1[tid][c2]);
        rowm[tid] = m;
    }
    __syncthreads();

#pragma unroll
    for (int i = 0; i < 8; i++) {
        const int t = m0 + ty*8 + i;
        const int s0 = n0 + tx*8;
        const float m = rowm[ty*8 + i];
        const float4 d0 = *(const float4*)(g_d + (size_t)t * TT + s0);
        const float4 d1 = *(const float4*)(g_d + (size_t)t * TT + s0 + 4);
        float dv[8] = {d0.x, d0.y, d0.z, d0.w, d1.x, d1.y, d1.z, d1.w};
        float e[8];
        float rs1 = 0.f, rs2 = 0.f, rs3 = 0.f;
#pragma unroll
        for (int j = 0; j < 8; j++) {
            if (s0 + j <= t) {
                const float xm = acc[i][j] - m;
                const float ee = __expf(xm);
                e[j] = ee;
                rs1 += ee;
                rs2 += ee * xm;
                rs3 += ee * dv[j];
            } else e[j] = 0.f;
        }
        float* lp = Lp + (size_t)t * TT + s0;
        *(float4*)lp       = make_float4(e[0], e[1], e[2], e[3]);
        *(float4*)(lp + 4) = make_float4(e[4], e[5], e[6], e[7]);
        red1[ty*8 + i][tx] = rs1;
        red2[ty*8 + i][tx] = rs2;
        red3[ty*8 + i][tx] = rs3;
    }
    __syncthreads();
    if (tid < 128) {
        float l1 = 0.f, l2 = 0.f, l3 = 0.f;
#pragma unroll
        for (int c2 = 0; c2 < 16; c2++) { l1 += red1[tid][c2]; l2 += red2[tid][c2]; l3 += red3[tid][c2]; }
        const size_t ix = ((size_t)bh * TT + m0 + tid) * 16 + jt;
        g_mp[ix] = rowm[tid];
        g_s1[ix] = l1;
        g_s2[ix] = l2;
        g_s3[ix] = l3;
    }
}

// ---------------------------------------------------------------------------
// K4: row stats + p = e*C (shifted vector attn stores) + energies + P@V
// ---------------------------------------------------------------------------
__global__ __launch_bounds__(256) void k_softmax_av(float* __restrict__ attn) {
    const int bh = blockIdx.y;
    const int t0 = (int)(gridDim.x - 1 - blockIdx.x) * 64;  // heavy first
    const int b = bh >> 4, h = bh & 15;
    const float* L = g_l + (size_t)bh * TT * TT;
    float* A = attn + (size_t)bh * TT * TT;
    const float* V = g_v + (size_t)bh * TT * DH;

    __shared__ float Cs2[64][16];
    __shared__ float Ps[64][68];
    __shared__ float Vs[64][68];
    __shared__ float sredA[64];
    __shared__ float sredB[64];

    const int tid = threadIdx.x;
    const int wid = tid >> 5, lane = tid & 31;
    const int ty = tid >> 4, tx = tid & 15;
    const int ntile = (t0 >> 7) + 1;

    if (tid < 64) {
        const size_t base = ((size_t)bh * TT + t0 + tid) * 16;
        float m = NEGINF;
        for (int j = 0; j < ntile; j++) m = fmaxf(m, g_mp[base + j]);
        float l = 0.f;
        for (int j = 0; j < ntile; j++) l += g_s1[base + j] * __expf(g_mp[base + j] - m);
        const float li = 1.f / l;
        const float ll = __logf(l);
        float ed = 0.f, ef = 0.f;
        for (int j = 0; j < ntile; j++) {
            const float dm = g_mp[base + j] - m;
            const float C = __expf(dm) * li;
            Cs2[tid][j] = C;
            ed += C * g_s3[base + j];
            ef += C * (g_s2[base + j] + (dm - ll) * g_s1[base + j]);
        }
        sredA[tid] = ed;
        sredB[tid] = ef;
    }
    __syncthreads();
    for (int s = 32; s; s >>= 1) {
        if (tid < s) { sredA[tid] += sredA[tid + s]; sredB[tid] += sredB[tid + s]; }
        __syncthreads();
    }
    if (tid == 0) {
        const int bid = blockIdx.y * 32 + blockIdx.x;
        g_edp[bid] = sredA[0];
        g_efp[bid] = sredB[0];
    }

    float acc[4][4];
#pragma unroll
    for (int i = 0; i < 4; i++)
#pragma unroll
        for (int j = 0; j < 4; j++) acc[i][j] = 0.f;

    const int nt = t0 + 64;
    for (int s0 = 0; s0 < nt; s0 += 64) {
        __syncthreads();
        const int jt = s0 >> 7;
        {
            const int rl = tid >> 2, cg = (tid & 3) * 16;
            const size_t g0 = (size_t)(t0 + rl) * TT + s0 + cg;
            const float Cc = Cs2[rl][jt];
            float pv[16];
#pragma unroll
            for (int q4 = 0; q4 < 4; q4++) {
                float4 e4 = *(const float4*)(L + g0 + q4*4);
                float4 p4 = make_float4(e4.x*Cc, e4.y*Cc, e4.z*Cc, e4.w*Cc);
                *(float4*)&Ps[rl][cg + q4*4] = p4;
                pv[q4*4+0] = p4.x; pv[q4*4+1] = p4.y;
                pv[q4*4+2] = p4.z; pv[q4*4+3] = p4.w;
            }
            A[g0] = pv[0];
            *(float4*)(A + g0 + 1)  = make_float4(pv[1],  pv[2],  pv[3],  pv[4]);
            *(float4*)(A + g0 + 5)  = make_float4(pv[5],  pv[6],  pv[7],  pv[8]);
            *(float4*)(A + g0 + 9)  = make_float4(pv[9],  pv[10], pv[11], pv[12]);
            *(float2*)(A + g0 + 13) = make_float2(pv[13], pv[14]);
            A[g0 + 15] = pv[15];
        }
#pragma unroll 4
        for (int e = tid; e < 1024; e += 256) {
            const int ss = e >> 4, d = (e & 15) * 4;
            *(float4*)&Vs[ss][d] = *(const float4*)(V + (size_t)(s0 + ss) * DH + d);
        }
        __syncthreads();
#pragma unroll 4
        for (int ss4 = 0; ss4 < 16; ss4++) {
            const float4 v0 = *(const float4*)&Vs[ss4*4+0][tx*4];
            const float4 v1 = *(const float4*)&Vs[ss4*4+1][tx*4];
            const float4 v2 = *(const float4*)&Vs[ss4*4+2][tx*4];
            const float4 v3 = *(const float4*)&Vs[ss4*4+3][tx*4];
#pragma unroll
            for (int i = 0; i < 4; i++) {
                const float4 pr = *(const float4*)&Ps[ty*4+i][ss4*4];
                acc[i][0] += pr.x*v0.x + pr.y*v1.x + pr.z*v2.x + pr.w*v3.x;
                acc[i][1] += pr.x*v0.y + pr.y*v1.y + pr.z*v2.y + pr.w*v3.y;
                acc[i][2] += pr.x*v0.z + pr.y*v1.z + pr.z*v2.z + pr.w*v3.z;
                acc[i][3] += pr.x*v0.w + pr.y*v1.w + pr.z*v2.w + pr.w*v3.w;
            }
        }
    }

    if (nt < TT) {
        const int nrem = TT - nt;
        const int n4 = (nrem - 4) >> 2;
        const float4 z4 = make_float4(0.f, 0.f, 0.f, 0.f);
        for (int rl = wid; rl < 64; rl += 8) {
            const size_t base = (size_t)(t0 + rl) * TT + nt;
            if (lane == 0) {
                A[base] = 0.f;
                A[base + 1 + 4*n4] = 0.f;
                A[base + 2 + 4*n4] = 0.f;
                A[base + 3 + 4*n4] = 0.f;
            }
            for (int i = lane; i < n4; i += 32)
                *(float4*)(A + base + 1 + 4*i) = z4;
        }
    }

#pragma unroll
    for (int i = 0; i < 4; i++) {
        const size_t row = (size_t)(b * TT + t0 + ty*4 + i) * CC + h * DH + tx * 4;
        *(float4*)(g_oh + row) = make_float4(acc[i][0], acc[i][1], acc[i][2], acc[i][3]);
    }
}

// ---------------------------------------------------------------------------
// K5: out = g_oh @ proj_w^T  (M=4096, N=1024, K=1024) SIMT, vector LDS
// ---------------------------------------------------------------------------
__global__ __launch_bounds__(256) void k_proj(const float* __restrict__ W,
                                              float* __restrict__ Cout) {
    __shared__ float As[16][132];
    __shared__ float Bs[16][132];
    const int tid = threadIdx.x;
    const int m0 = blockIdx.y * 128;
    const int n0 = blockIdx.x * 128;
    const int r  = tid >> 2;
    const int c4 = (tid & 3) * 4;
    const int ty = tid >> 4;
    const int tx = tid & 15;

    float acc[8][8];
#pragma unroll
    for (int i = 0; i < 8; i++)
#pragma unroll
        for (int j = 0; j < 8; j++) acc[i][j] = 0.f;

    for (int k0 = 0; k0 < 1024; k0 += 16) {
        float4 a0 = *(const float4*)(g_oh + (size_t)(m0 + r)      * 1024 + k0 + c4);
        float4 a1 = *(const float4*)(g_oh + (size_t)(m0 + r + 64) * 1024 + k0 + c4);
        float4 b0 = *(const float4*)(W    + (size_t)(n0 + r)      * 1024 + k0 + c4);
        float4 b1 = *(const float4*)(W    + (size_t)(n0 + r + 64) * 1024 + k0 + c4);
        __syncthreads();
        As[c4+0][r] = a0.x; As[c4+1][r] = a0.y; As[c4+2][r] = a0.z; As[c4+3][r] = a0.w;
        As[c4+0][r+64] = a1.x; As[c4+1][r+64] = a1.y; As[c4+2][r+64] = a1.z; As[c4+3][r+64] = a1.w;
        Bs[c4+0][r] = b0.x; Bs[c4+1][r] = b0.y; Bs[c4+2][r] = b0.z; Bs[c4+3][r] = b0.w;
        Bs[c4+0][r+64] = b1.x; Bs[c4+1][r+64] = b1.y; Bs[c4+2][r+64] = b1.z; Bs[c4+3][r+64] = b1.w;
        __syncthreads();
#pragma unroll
        for (int kk = 0; kk < 16; kk++) {
            float ra[8], rb[8];
            LOAD_FRAG8(ra, As, kk, ty*8);
            LOAD_FRAG8(rb, Bs, kk, tx*8);
#pragma unroll
            for (int i = 0; i < 8; i++)
#pragma unroll
                for (int j = 0; j < 8; j++)
                    acc[i][j] += ra[i] * rb[j];
        }
    }

#pragma unroll
    for (int i = 0; i < 8; i++) {
        float* base = Cout + (size_t)(m0 + ty*8 + i) * 1024 + n0 + tx*8;
        *(float4*)base       = make_float4(acc[i][0], acc[i][1], acc[i][2], acc[i][3]);
        *(float4*)(base + 4) = make_float4(acc[i][4], acc[i][5], acc[i][6], acc[i][7]);
    }
}

// ---------------------------------------------------------------------------
// K6: deterministic scalar finalize
// ---------------------------------------------------------------------------
__global__ void k_finalize(float* __restrict__ scal) {
    if (threadIdx.x == 0 && blockIdx.x == 0) {
        double rep = 0.0;
        for (int i = 0; i < TT; i++) rep += (double)g_repp[i];
        double de = 0.0, fe = 0.0;
        for (int i = 0; i < 1024; i++) { de += (double)g_edp[i]; fe += (double)g_efp[i]; }
        const double nrows = (double)BB * HH * TT;
        scal[0] = (float)(de / nrows);
        scal[1] = (float)(-fe / nrows);
        scal[2] = (float)(rep / ((double)TT * TT - TT));
    }
}

// ---------------------------------------------------------------------------
extern "C" void kernel_launch(void* const* d_in, const int* in_sizes, int n_in,
                              void* d_out, int out_size) {
    const float* x      = (const float*)d_in[0];
    const float* qkv_w  = (const float*)d_in[1];
    const float* proj_w = (const float*)d_in[2];
    const float* pos    = (const float*)d_in[3];
    float* out   = (float*)d_out;
    float* attn  = out + ATTN_OFF;
    float* dists = out + DIST_OFF;

    k_qkv<<<dim3(24, 32), 256>>>(x, qkv_w);        // 1
    k_dists<<<TT, 256>>>(pos, dists);              // 2
    k_noop<<<1, 32>>>();                           // 3 (spacer)
    k_logits<<<dim3(136, 32), 256>>>();            // 4 → profiled
    k_softmax_av<<<dim3(32, 32), 256>>>(attn);     // 5
    k_proj<<<dim3(8, 32), 256>>>(proj_w, out);     // 6
    k_finalize<<<1, 32>>>(out + SCAL_OFF);         // 7
}